// round 1
// baseline (speedup 1.0000x reference)
#include <cuda_runtime.h>
#include <math.h>

// Problem constants
#define Bv 2
#define Sv 2048
#define Ev 1024
#define Hv 16
#define Dv 64
#define N3 3072           // 3*E
#define BHD ((size_t)Bv*Hv*Sv*Dv)   // 4,194,304

// ---------------- device scratch (static, allocation-free) ----------------
__device__ float g_Q[Bv*Hv*Sv*Dv];
__device__ float g_K[Bv*Hv*Sv*Dv];
__device__ float g_V[Bv*Hv*Sv*Dv];
__device__ float g_AO[Bv*Sv*Ev];
// Fallback weights scratch in case d_out only holds attn_out
__device__ float g_Wscratch[(size_t)Bv*Hv*Sv*Sv];

// ============================================================
// Kernel 1: QKV GEMM  [4096,1024] @ [1024,3072] + bias
// 128x128x8 tiles, 256 threads, 8x8 microtile.
// Epilogue scatters into g_Q/g_K/g_V in [B,H,S,D] layout.
// ============================================================
__global__ void __launch_bounds__(256) qkv_gemm(const float* __restrict__ A,
                                                const float* __restrict__ W,
                                                const float* __restrict__ bias) {
    const int M = Bv * Sv;     // 4096
    const int N = N3;          // 3072
    const int K = Ev;          // 1024
    __shared__ float As[8][128];
    __shared__ float Bs[8][128];

    int bx = blockIdx.x;       // N tile
    int by = blockIdx.y;       // M tile
    int tid = threadIdx.x;
    int tr = tid / 16;         // 0..15
    int tc = tid % 16;         // 0..15

    float acc[8][8];
#pragma unroll
    for (int i = 0; i < 8; i++)
#pragma unroll
        for (int j = 0; j < 8; j++) acc[i][j] = 0.f;

    int arow = tid >> 1;            // 0..127
    int acol = (tid & 1) * 4;       // 0 or 4
    int brow = tid >> 5;            // 0..7
    int bcol = (tid & 31) * 4;      // 0..124

    const float* Aptr = A + (size_t)(by * 128) * K;
    const float* Wptr = W + bx * 128;

    for (int k0 = 0; k0 < K; k0 += 8) {
        float4 a = *(const float4*)(Aptr + (size_t)arow * K + k0 + acol);
        As[acol + 0][arow] = a.x;
        As[acol + 1][arow] = a.y;
        As[acol + 2][arow] = a.z;
        As[acol + 3][arow] = a.w;
        *(float4*)&Bs[brow][bcol] =
            *(const float4*)(Wptr + (size_t)(k0 + brow) * N + bcol);
        __syncthreads();
#pragma unroll
        for (int kk = 0; kk < 8; kk++) {
            float ra[8], rb[8];
            *(float4*)&ra[0] = *(const float4*)&As[kk][tr * 8];
            *(float4*)&ra[4] = *(const float4*)&As[kk][tr * 8 + 4];
            *(float4*)&rb[0] = *(const float4*)&Bs[kk][tc * 8];
            *(float4*)&rb[4] = *(const float4*)&Bs[kk][tc * 8 + 4];
#pragma unroll
            for (int i = 0; i < 8; i++)
#pragma unroll
                for (int j = 0; j < 8; j++) acc[i][j] += ra[i] * rb[j];
        }
        __syncthreads();
    }

    // Scatter epilogue
#pragma unroll
    for (int i = 0; i < 8; i++) {
        int m = by * 128 + tr * 8 + i;
        int b = m / Sv, s = m % Sv;
#pragma unroll
        for (int j = 0; j < 8; j++) {
            int n = bx * 128 + tc * 8 + j;
            float v = acc[i][j] + bias[n];
            int which = n >> 10;          // 0=q 1=k 2=v
            int e = n & 1023;
            int h = e >> 6;
            int d = e & 63;
            size_t dst = (((size_t)b * Hv + h) * Sv + s) * Dv + d;
            if (which == 0) g_Q[dst] = v;
            else if (which == 1) g_K[dst] = v;
            else g_V[dst] = v;
        }
    }
}

// ============================================================
// Kernel 2: scores = (Q K^T) * 1/8 with causal mask (masked -> 0.0)
// Per (b,h): [2048,64] x [64,2048]. K-dim = 64 fits in smem once.
// Dynamic smem: QsT[64][128] + KsT[64][128] = 64 KB.
// ============================================================
__global__ void __launch_bounds__(256) scores_kernel(float* __restrict__ Wout) {
    int bh = blockIdx.z;
    int c0 = blockIdx.x * 128;   // key tile
    int r0 = blockIdx.y * 128;   // query tile
    float* out = Wout + (size_t)bh * Sv * Sv;
    int tid = threadIdx.x;

    if (c0 > r0 + 127) {
        // Fully masked tile: exp underflows to exactly 0 -> write zeros.
        float4 z = make_float4(0.f, 0.f, 0.f, 0.f);
#pragma unroll
        for (int it = 0; it < 16; it++) {
            int idx = tid + it * 256;          // 4096 float4
            int row = idx >> 5;                // 32 float4 per row
            int c4 = idx & 31;
            *(float4*)(out + (size_t)(r0 + row) * Sv + c0 + c4 * 4) = z;
        }
        return;
    }

    extern __shared__ float sm[];
    float(*QsT)[128] = (float(*)[128])sm;             // [64][128]
    float(*KsT)[128] = (float(*)[128])(sm + 64 * 128);

    const float* Q = g_Q + (size_t)bh * Sv * Dv;
    const float* Kp = g_K + (size_t)bh * Sv * Dv;

#pragma unroll
    for (int it = 0; it < 8; it++) {
        int idx = tid + it * 256;      // 2048 float4 per tensor
        int row = idx >> 4;            // 0..127
        int k4 = idx & 15;             // 0..15
        float4 q = *(const float4*)(Q + (size_t)(r0 + row) * Dv + k4 * 4);
        QsT[k4 * 4 + 0][row] = q.x;
        QsT[k4 * 4 + 1][row] = q.y;
        QsT[k4 * 4 + 2][row] = q.z;
        QsT[k4 * 4 + 3][row] = q.w;
        float4 k = *(const float4*)(Kp + (size_t)(c0 + row) * Dv + k4 * 4);
        KsT[k4 * 4 + 0][row] = k.x;
        KsT[k4 * 4 + 1][row] = k.y;
        KsT[k4 * 4 + 2][row] = k.z;
        KsT[k4 * 4 + 3][row] = k.w;
    }
    __syncthreads();

    int tr = tid / 16, tc = tid % 16;
    float acc[8][8];
#pragma unroll
    for (int i = 0; i < 8; i++)
#pragma unroll
        for (int j = 0; j < 8; j++) acc[i][j] = 0.f;

#pragma unroll 16
    for (int kk = 0; kk < 64; kk++) {
        float ra[8], rb[8];
        *(float4*)&ra[0] = *(const float4*)&QsT[kk][tr * 8];
        *(float4*)&ra[4] = *(const float4*)&QsT[kk][tr * 8 + 4];
        *(float4*)&rb[0] = *(const float4*)&KsT[kk][tc * 8];
        *(float4*)&rb[4] = *(const float4*)&KsT[kk][tc * 8 + 4];
#pragma unroll
        for (int i = 0; i < 8; i++)
#pragma unroll
            for (int j = 0; j < 8; j++) acc[i][j] += ra[i] * rb[j];
    }

    const float scale = 0.125f;   // 1/sqrt(64)
#pragma unroll
    for (int i = 0; i < 8; i++) {
        int r = r0 + tr * 8 + i;
        float vals[8];
#pragma unroll
        for (int j = 0; j < 8; j++) {
            int c = c0 + tc * 8 + j;
            vals[j] = (c <= r) ? acc[i][j] * scale : 0.f;
        }
        float* op = out + (size_t)r * Sv + c0 + tc * 8;
        *(float4*)op = make_float4(vals[0], vals[1], vals[2], vals[3]);
        *(float4*)(op + 4) = make_float4(vals[4], vals[5], vals[6], vals[7]);
    }
}

// ============================================================
// Kernel 3: in-place row softmax over the first (q+1) entries.
// One warp per row; full row held in registers (64 f32/lane).
// Masked entries (j > q) stay exactly 0.
// ============================================================
__global__ void __launch_bounds__(256) softmax_kernel(float* __restrict__ W) {
    int gwarp = (blockIdx.x * 256 + threadIdx.x) >> 5;
    int lane = threadIdx.x & 31;
    int bh = gwarp >> 11;            // / 2048
    int q = gwarp & 2047;
    float* row = W + ((size_t)bh * Sv + q) * Sv;
    int L = q + 1;

    float4 v[16];
    float mx = -1e30f;
#pragma unroll
    for (int it = 0; it < 16; it++) {
        int j = (it * 32 + lane) * 4;
        if (j < L) {
            v[it] = *(const float4*)(row + j);
            mx = fmaxf(mx, v[it].x);
            if (j + 1 < L) mx = fmaxf(mx, v[it].y);
            if (j + 2 < L) mx = fmaxf(mx, v[it].z);
            if (j + 3 < L) mx = fmaxf(mx, v[it].w);
        } else {
            v[it] = make_float4(0.f, 0.f, 0.f, 0.f);
        }
    }
#pragma unroll
    for (int o = 16; o; o >>= 1) mx = fmaxf(mx, __shfl_xor_sync(0xffffffffu, mx, o));

    float sum = 0.f;
#pragma unroll
    for (int it = 0; it < 16; it++) {
        int j = (it * 32 + lane) * 4;
        float e0 = (j + 0 < L) ? __expf(v[it].x - mx) : 0.f;
        float e1 = (j + 1 < L) ? __expf(v[it].y - mx) : 0.f;
        float e2 = (j + 2 < L) ? __expf(v[it].z - mx) : 0.f;
        float e3 = (j + 3 < L) ? __expf(v[it].w - mx) : 0.f;
        v[it] = make_float4(e0, e1, e2, e3);
        sum += e0 + e1 + e2 + e3;
    }
#pragma unroll
    for (int o = 16; o; o >>= 1) sum += __shfl_xor_sync(0xffffffffu, sum, o);
    float inv = 1.0f / sum;

#pragma unroll
    for (int it = 0; it < 16; it++) {
        int j = (it * 32 + lane) * 4;
        if (j + 3 < L) {
            *(float4*)(row + j) = make_float4(v[it].x * inv, v[it].y * inv,
                                              v[it].z * inv, v[it].w * inv);
        } else if (j < L) {
            row[j] = v[it].x * inv;
            if (j + 1 < L) row[j + 1] = v[it].y * inv;
            if (j + 2 < L) row[j + 2] = v[it].z * inv;
        }
    }
}

// ============================================================
// Kernel 4: attn_out(pre-proj) = P @ V per (b,h).
// Tile 128 rows x 64 cols (full D). Causal-truncated K loop.
// ============================================================
__global__ void __launch_bounds__(256) pv_kernel(const float* __restrict__ W) {
    int bh = blockIdx.y;
    int r0 = blockIdx.x * 128;
    const float* P = W + (size_t)bh * Sv * Sv;
    const float* V = g_V + (size_t)bh * Sv * Dv;

    __shared__ float Ps[128][36];   // pad 36: keeps float4 store alignment
    __shared__ float Vs[32][64];

    int tid = threadIdx.x;
    int tr = tid / 16, tc = tid % 16;
    float acc[8][4];
#pragma unroll
    for (int i = 0; i < 8; i++)
#pragma unroll
        for (int j = 0; j < 4; j++) acc[i][j] = 0.f;

    int kend = r0 + 128;   // rows beyond the diagonal are exact zeros
    for (int kc = 0; kc < kend; kc += 32) {
#pragma unroll
        for (int it = 0; it < 4; it++) {
            int idx = tid + it * 256;      // 1024 float4
            int row = idx >> 3;            // 0..127
            int c4 = idx & 7;              // 0..7
            float4 p = *(const float4*)(P + (size_t)(r0 + row) * Sv + kc + c4 * 4);
            *(float4*)&Ps[row][c4 * 4] = p;
        }
#pragma unroll
        for (int it = 0; it < 2; it++) {
            int idx = tid + it * 256;      // 512 float4
            int row = idx >> 4;            // 0..31
            int c4 = idx & 15;             // 0..15
            *(float4*)&Vs[row][c4 * 4] =
                *(const float4*)(V + (size_t)(kc + row) * Dv + c4 * 4);
        }
        __syncthreads();
#pragma unroll
        for (int kk = 0; kk < 32; kk++) {
            float4 v4 = *(const float4*)&Vs[kk][tc * 4];
            float p[8];
#pragma unroll
            for (int i = 0; i < 8; i++) p[i] = Ps[tr * 8 + i][kk];
#pragma unroll
            for (int i = 0; i < 8; i++) {
                acc[i][0] += p[i] * v4.x;
                acc[i][1] += p[i] * v4.y;
                acc[i][2] += p[i] * v4.z;
                acc[i][3] += p[i] * v4.w;
            }
        }
        __syncthreads();
    }

    int b = bh >> 4, h = bh & 15;
#pragma unroll
    for (int i = 0; i < 8; i++) {
        int r = r0 + tr * 8 + i;
        float4 o = make_float4(acc[i][0], acc[i][1], acc[i][2], acc[i][3]);
        *(float4*)(g_AO + ((size_t)(b * Sv + r) * Ev) + h * Dv + tc * 4) = o;
    }
}

// ============================================================
// Kernel 5: projection  g_AO[4096,1024] @ w_proj[1024,1024] + b_proj
// -> d_out attn_out region (row-major [B,S,E]).
// ============================================================
__global__ void __launch_bounds__(256) proj_gemm(const float* __restrict__ W,
                                                 const float* __restrict__ bias,
                                                 float* __restrict__ C) {
    const int N = Ev;          // 1024
    const int K = Ev;          // 1024
    __shared__ float As[8][128];
    __shared__ float Bs[8][128];

    int bx = blockIdx.x;
    int by = blockIdx.y;
    int tid = threadIdx.x;
    int tr = tid / 16, tc = tid % 16;

    float acc[8][8];
#pragma unroll
    for (int i = 0; i < 8; i++)
#pragma unroll
        for (int j = 0; j < 8; j++) acc[i][j] = 0.f;

    int arow = tid >> 1;
    int acol = (tid & 1) * 4;
    int brow = tid >> 5;
    int bcol = (tid & 31) * 4;

    const float* Aptr = g_AO + (size_t)(by * 128) * K;
    const float* Wptr = W + bx * 128;

    for (int k0 = 0; k0 < K; k0 += 8) {
        float4 a = *(const float4*)(Aptr + (size_t)arow * K + k0 + acol);
        As[acol + 0][arow] = a.x;
        As[acol + 1][arow] = a.y;
        As[acol + 2][arow] = a.z;
        As[acol + 3][arow] = a.w;
        *(float4*)&Bs[brow][bcol] =
            *(const float4*)(Wptr + (size_t)(k0 + brow) * N + bcol);
        __syncthreads();
#pragma unroll
        for (int kk = 0; kk < 8; kk++) {
            float ra[8], rb[8];
            *(float4*)&ra[0] = *(const float4*)&As[kk][tr * 8];
            *(float4*)&ra[4] = *(const float4*)&As[kk][tr * 8 + 4];
            *(float4*)&rb[0] = *(const float4*)&Bs[kk][tc * 8];
            *(float4*)&rb[4] = *(const float4*)&Bs[kk][tc * 8 + 4];
#pragma unroll
            for (int i = 0; i < 8; i++)
#pragma unroll
                for (int j = 0; j < 8; j++) acc[i][j] += ra[i] * rb[j];
        }
        __syncthreads();
    }

    float bsv[8];
#pragma unroll
    for (int j = 0; j < 8; j++) bsv[j] = bias[bx * 128 + tc * 8 + j];

#pragma unroll
    for (int i = 0; i < 8; i++) {
        int m = by * 128 + tr * 8 + i;
        float* cr = C + (size_t)m * N + bx * 128 + tc * 8;
        *(float4*)cr = make_float4(acc[i][0] + bsv[0], acc[i][1] + bsv[1],
                                   acc[i][2] + bsv[2], acc[i][3] + bsv[3]);
        *(float4*)(cr + 4) = make_float4(acc[i][4] + bsv[4], acc[i][5] + bsv[5],
                                         acc[i][6] + bsv[6], acc[i][7] + bsv[7]);
    }
}

// ============================================================
// Launch
// ============================================================
extern "C" void kernel_launch(void* const* d_in, const int* in_sizes, int n_in,
                              void* d_out, int out_size) {
    const float* hs     = (const float*)d_in[0];
    const float* w_attn = (const float*)d_in[1];
    const float* b_attn = (const float*)d_in[2];
    const float* w_proj = (const float*)d_in[3];
    const float* b_proj = (const float*)d_in[4];
    float* out = (float*)d_out;

    const size_t AO_N = (size_t)Bv * Sv * Ev;               // 4,194,304
    const size_t W_N  = (size_t)Bv * Hv * Sv * Sv;          // 134,217,728

    float* wts;
    if ((size_t)out_size >= AO_N + W_N) {
        wts = out + AO_N;          // weights live directly in d_out
    } else {
        void* p = nullptr;
        cudaGetSymbolAddress(&p, g_Wscratch);
        wts = (float*)p;
    }

    // scores kernel needs 64 KB dynamic smem
    cudaFuncSetAttribute(scores_kernel,
                         cudaFuncAttributeMaxDynamicSharedMemorySize, 65536);

    qkv_gemm<<<dim3(N3 / 128, (Bv * Sv) / 128), 256>>>(hs, w_attn, b_attn);
    scores_kernel<<<dim3(Sv / 128, Sv / 128, Bv * Hv), 256, 65536>>>(wts);
    softmax_kernel<<<(Bv * Hv * Sv) / 8, 256>>>(wts);
    pv_kernel<<<dim3(Sv / 128, Bv * Hv), 256>>>(wts);
    proj_gemm<<<dim3(Ev / 128, (Bv * Sv) / 128), 256>>>(w_proj, b_proj, out);
}